// round 6
// baseline (speedup 1.0000x reference)
#include <cuda_runtime.h>
#include <cuda_bf16.h>

// Problem constants (fixed by setup_inputs)
#define L    4096
#define H    16
#define P    128
#define NS   256      // d_state
#define CH   256      // chunk
#define NC   16       // chunks per sequence
#define BD   4        // 2*b direction-batches (0,1 fwd ; 2,3 bwd)
#define DIN  2048

// ---------------- scratch (static device globals; no runtime allocation) ----
__device__ __align__(16) float g_dtw[BD * L * H];                 // softplus(dt), flipped layout
__device__ __align__(16) float g_cs [BD * L * H];                 // per-chunk inclusive cumsum of dt*A
__device__ __align__(16) float g_CB [BD * NC * CH * CH];          // C @ B^T per chunk (67MB)
__device__ __align__(16) float g_y  [(size_t)BD * L * DIN];       // y_intra + y_inter (134MB)
__device__ __align__(16) float g_st [(size_t)BD * NC * H * NS * P]; // states -> prev (134MB)

// ---------------------------------------------------------------------------
// K1: softplus(dt) and per-chunk cumsum of dA = dt*A, in flipped (bd) layout.
// grid (NC, BD), 256 threads (= chunk positions)
// ---------------------------------------------------------------------------
__global__ void k_prep(const float* __restrict__ dt, const float* __restrict__ A_log)
{
    int j  = blockIdx.x;
    int bd = blockIdx.y;
    int i  = threadIdx.x;
    bool rev = (bd >= 2);
    int bb = rev ? bd - 2 : bd;
    int t  = j * CH + i;
    int to = rev ? (L - 1 - t) : t;
    __shared__ float s[CH];

    for (int h = 0; h < H; h++) {
        int col = rev ? (H + h) : h;
        float v  = dt[(size_t)(bb * L + to) * (2 * H) + col];
        // stable softplus
        float sp = fmaxf(v, 0.f) + log1pf(expf(-fabsf(v)));
        g_dtw[(size_t)(bd * L + t) * H + h] = sp;
        float a  = -expf(A_log[h]);
        float dA = sp * a;
        s[i] = dA;
        __syncthreads();
        #pragma unroll
        for (int off = 1; off < CH; off <<= 1) {
            float add = (i >= off) ? s[i - off] : 0.f;
            __syncthreads();
            s[i] += add;
            __syncthreads();
        }
        g_cs[(size_t)(bd * L + t) * H + h] = s[i];
        __syncthreads();
    }
}

// ---------------------------------------------------------------------------
// K2: CB[bd,j,i,k] = sum_n C[i,n] * B[k,n]   (shared across heads)
// grid (4 i-tiles, 4 k-tiles, 64 bd*j), 256 threads, 4x4 micro-tile
// ---------------------------------------------------------------------------
__global__ void k_cb(const float* __restrict__ BC)
{
    int ti = blockIdx.x, tk = blockIdx.y;
    int bd = blockIdx.z >> 4, j = blockIdx.z & 15;
    bool rev = (bd >= 2); int bb = rev ? bd - 2 : bd;
    int tbase = j * CH;

    __shared__ float Cs[64][33];
    __shared__ float Bs[64][33];

    int tid = threadIdx.x;
    int ty = tid >> 4, tx = tid & 15;
    float acc[4][4];
    #pragma unroll
    for (int a = 0; a < 4; a++)
        #pragma unroll
        for (int b = 0; b < 4; b++) acc[a][b] = 0.f;

    for (int n0 = 0; n0 < NS; n0 += 32) {
        #pragma unroll
        for (int r = 0; r < 8; r++) {
            int e = tid + 256 * r;
            int row = e >> 5, col = e & 31;
            int tC = tbase + ti * 64 + row; int toC = rev ? (L - 1 - tC) : tC;
            Cs[row][col] = BC[(size_t)(bb * L + toC) * (2 * NS) + NS + n0 + col];
            int tB = tbase + tk * 64 + row; int toB = rev ? (L - 1 - tB) : tB;
            Bs[row][col] = BC[(size_t)(bb * L + toB) * (2 * NS) + n0 + col];
        }
        __syncthreads();
        #pragma unroll 8
        for (int n = 0; n < 32; n++) {
            float cv[4], bv[4];
            #pragma unroll
            for (int a = 0; a < 4; a++) cv[a] = Cs[ty * 4 + a][n];
            #pragma unroll
            for (int b = 0; b < 4; b++) bv[b] = Bs[tx * 4 + b][n];
            #pragma unroll
            for (int a = 0; a < 4; a++)
                #pragma unroll
                for (int b = 0; b < 4; b++) acc[a][b] += cv[a] * bv[b];
        }
        __syncthreads();
    }
    #pragma unroll
    for (int a = 0; a < 4; a++)
        #pragma unroll
        for (int b = 0; b < 4; b++)
            g_CB[((size_t)(bd * NC + j) * CH + ti * 64 + ty * 4 + a) * CH + tk * 64 + tx * 4 + b] = acc[a][b];
}

// ---------------------------------------------------------------------------
// K3: y_intra[i,p] = sum_{k<=i} CB[i,k] exp(cs_i - cs_k) dt_k x[k,p]
// grid (4 i-tiles, H, 64 bd*j), 256 threads; writes g_y ("=")
// ---------------------------------------------------------------------------
__global__ void __launch_bounds__(256) k_yintra(const float* __restrict__ x)
{
    int it = blockIdx.x;
    int h  = blockIdx.y;
    int bd = blockIdx.z >> 4, j = blockIdx.z & 15;
    bool rev = (bd >= 2); int bb = rev ? bd - 2 : bd;
    int tbase = j * CH;
    int tid = threadIdx.x;

    __shared__ __align__(16) float Xs[64 * 128];   // [k][p]
    __shared__ __align__(16) float Gs[64 * 64];    // [i][k]

    int ty = tid >> 5, tx = tid & 31;
    float acc[8][4];
    #pragma unroll
    for (int r = 0; r < 8; r++)
        #pragma unroll
        for (int c = 0; c < 4; c++) acc[r][c] = 0.f;

    const float* csb = g_cs  + (size_t)(bd * L + tbase) * H + h;
    const float* dtb = g_dtw + (size_t)(bd * L + tbase) * H + h;
    const float* cbb = g_CB + (size_t)(bd * NC + j) * CH * CH;
    int kloc = tid & 63;
    int ib   = tid >> 6;

    for (int kt = 0; kt <= it; kt++) {
        // X tile: 64k x 128p
        #pragma unroll
        for (int r = 0; r < 8; r++) {
            int e4 = tid + 256 * r;
            int k = e4 >> 5, p4 = e4 & 31;
            int tt = tbase + kt * 64 + k;
            int to = rev ? (L - 1 - tt) : tt;
            reinterpret_cast<float4*>(Xs)[e4] =
                reinterpret_cast<const float4*>(x + (size_t)(bb * L + to) * DIN + h * P)[p4];
        }
        // G tile
        {
            int kk = kt * 64 + kloc;
            float csk = csb[kk * H];
            float dtk = dtb[kk * H];
            #pragma unroll
            for (int r = 0; r < 16; r++) {
                int iloc = ib + 4 * r;
                int ii = it * 64 + iloc;
                float g = 0.f;
                if (kk <= ii) {
                    float csi = csb[ii * H];
                    g = cbb[(size_t)ii * CH + kk] * __expf(csi - csk) * dtk;
                }
                Gs[iloc * 64 + kloc] = g;
            }
        }
        __syncthreads();
        #pragma unroll 4
        for (int k = 0; k < 64; k++) {
            float4 xv = reinterpret_cast<const float4*>(Xs)[k * 32 + tx];
            #pragma unroll
            for (int r = 0; r < 8; r++) {
                float gv = Gs[(ty * 8 + r) * 64 + k];
                acc[r][0] += gv * xv.x; acc[r][1] += gv * xv.y;
                acc[r][2] += gv * xv.z; acc[r][3] += gv * xv.w;
            }
        }
        __syncthreads();
    }
    #pragma unroll
    for (int r = 0; r < 8; r++) {
        int ii = it * 64 + ty * 8 + r;
        float4 o = make_float4(acc[r][0], acc[r][1], acc[r][2], acc[r][3]);
        reinterpret_cast<float4*>(g_y + (size_t)(bd * L + tbase + ii) * DIN + h * P)[tx] = o;
    }
}

// ---------------------------------------------------------------------------
// K4: states[n,p] = sum_k B[k,n] * exp(cs_last - cs_k) dt_k x[k,p]
// grid (4 n-tiles, H, 64 bd*j)
// ---------------------------------------------------------------------------
__global__ void __launch_bounds__(256) k_states(const float* __restrict__ x,
                                                const float* __restrict__ BC)
{
    int nt = blockIdx.x;
    int h  = blockIdx.y;
    int bd = blockIdx.z >> 4, j = blockIdx.z & 15;
    bool rev = (bd >= 2); int bb = rev ? bd - 2 : bd;
    int tbase = j * CH;
    int tid = threadIdx.x;

    __shared__ __align__(16) float XWs[64 * 128]; // [k][p]  (w*x)
    __shared__ __align__(16) float Bs[64 * 64];   // [k][n]

    int ty = tid >> 5, tx = tid & 31;
    float acc[8][4];
    #pragma unroll
    for (int r = 0; r < 8; r++)
        #pragma unroll
        for (int c = 0; c < 4; c++) acc[r][c] = 0.f;

    const float* csb = g_cs  + (size_t)(bd * L + tbase) * H + h;
    const float* dtb = g_dtw + (size_t)(bd * L + tbase) * H + h;
    float cslast = csb[255 * H];

    for (int kt = 0; kt < 4; kt++) {
        #pragma unroll
        for (int r = 0; r < 8; r++) {
            int e4 = tid + 256 * r;
            int k = e4 >> 5, p4 = e4 & 31;
            int kk = kt * 64 + k;
            int tt = tbase + kk;
            int to = rev ? (L - 1 - tt) : tt;
            float w = __expf(cslast - csb[kk * H]) * dtb[kk * H];
            float4 xv = reinterpret_cast<const float4*>(x + (size_t)(bb * L + to) * DIN + h * P)[p4];
            xv.x *= w; xv.y *= w; xv.z *= w; xv.w *= w;
            reinterpret_cast<float4*>(XWs)[e4] = xv;
        }
        #pragma unroll
        for (int r = 0; r < 4; r++) {
            int e4 = tid + 256 * r;
            int k = e4 >> 4, n4 = e4 & 15;
            int tt = tbase + kt * 64 + k;
            int to = rev ? (L - 1 - tt) : tt;
            reinterpret_cast<float4*>(Bs)[e4] =
                reinterpret_cast<const float4*>(BC + (size_t)(bb * L + to) * (2 * NS))[nt * 16 + n4];
        }
        __syncthreads();
        #pragma unroll 4
        for (int k = 0; k < 64; k++) {
            float4 xv = reinterpret_cast<const float4*>(XWs)[k * 32 + tx];
            float4 b0 = reinterpret_cast<const float4*>(Bs)[k * 16 + ty * 2];
            float4 b1 = reinterpret_cast<const float4*>(Bs)[k * 16 + ty * 2 + 1];
            float bs[8] = {b0.x, b0.y, b0.z, b0.w, b1.x, b1.y, b1.z, b1.w};
            #pragma unroll
            for (int r = 0; r < 8; r++) {
                acc[r][0] += bs[r] * xv.x; acc[r][1] += bs[r] * xv.y;
                acc[r][2] += bs[r] * xv.z; acc[r][3] += bs[r] * xv.w;
            }
        }
        __syncthreads();
    }
    #pragma unroll
    for (int r = 0; r < 8; r++) {
        int n = nt * 64 + ty * 8 + r;
        float4 o = make_float4(acc[r][0], acc[r][1], acc[r][2], acc[r][3]);
        reinterpret_cast<float4*>(g_st)[(((size_t)(bd * NC + j) * H + h) * NS + n) * 32 + tx] = o;
    }
}

// ---------------------------------------------------------------------------
// K5: sequential inter-chunk scan (in-place: states -> prev-at-chunk-start)
// one thread per (bd,h,n,p); grid 8192 * 256 = 2^21 threads
// ---------------------------------------------------------------------------
__global__ void k_scan()
{
    int g = blockIdx.x * 256 + threadIdx.x;
    int bd = g >> 19;
    int inner = g & ((1 << 19) - 1);
    int h = inner >> 15;
    const float* csb = g_cs + (size_t)(bd * L) * H + h;
    float* base = g_st + ((size_t)bd << 23) + inner;
    float carry = 0.f;
    #pragma unroll
    for (int j = 0; j < NC; j++) {
        float s = base[(size_t)j << 19];
        base[(size_t)j << 19] = carry;                  // prev[j] = carry before update
        float cd = __expf(csb[(j * CH + 255) * H]);     // chunk decay of chunk j
        carry = carry * cd + s;
    }
}

// ---------------------------------------------------------------------------
// K6: y_inter[i,p] = exp(cs_i) * sum_n C[i,n] prev[n,p]   (adds into g_y)
// grid (4 i-tiles, H, 64 bd*j)
// ---------------------------------------------------------------------------
__global__ void __launch_bounds__(256) k_yinter(const float* __restrict__ BC)
{
    int it = blockIdx.x;
    int h  = blockIdx.y;
    int bd = blockIdx.z >> 4, j = blockIdx.z & 15;
    bool rev = (bd >= 2); int bb = rev ? bd - 2 : bd;
    int tbase = j * CH;
    int tid = threadIdx.x;

    __shared__ __align__(16) float Ps[64 * 128];  // [n][p] prev tile
    __shared__ __align__(16) float Cs[64 * 64];   // [i][n]

    int ty = tid >> 5, tx = tid & 31;
    float acc[8][4];
    #pragma unroll
    for (int r = 0; r < 8; r++)
        #pragma unroll
        for (int c = 0; c < 4; c++) acc[r][c] = 0.f;

    const float* stb = g_st + (((size_t)(bd * NC + j)) * H + h) * NS * P;

    for (int nt = 0; nt < 4; nt++) {
        #pragma unroll
        for (int r = 0; r < 4; r++) {
            int e4 = tid + 256 * r;
            int i = e4 >> 4, n4 = e4 & 15;
            int tt = tbase + it * 64 + i;
            int to = rev ? (L - 1 - tt) : tt;
            reinterpret_cast<float4*>(Cs)[e4] =
                reinterpret_cast<const float4*>(BC + (size_t)(bb * L + to) * (2 * NS) + NS)[nt * 16 + n4];
        }
        #pragma unroll
        for (int r = 0; r < 8; r++) {
            int e4 = tid + 256 * r;
            int nn = e4 >> 5, p4 = e4 & 31;
            reinterpret_cast<float4*>(Ps)[e4] =
                reinterpret_cast<const float4*>(stb + (size_t)(nt * 64 + nn) * P)[p4];
        }
        __syncthreads();
        #pragma unroll 4
        for (int n = 0; n < 64; n++) {
            float4 xv = reinterpret_cast<const float4*>(Ps)[n * 32 + tx];
            #pragma unroll
            for (int r = 0; r < 8; r++) {
                float cv = Cs[(ty * 8 + r) * 64 + n];
                acc[r][0] += cv * xv.x; acc[r][1] += cv * xv.y;
                acc[r][2] += cv * xv.z; acc[r][3] += cv * xv.w;
            }
        }
        __syncthreads();
    }
    const float* csb = g_cs + (size_t)(bd * L + tbase) * H + h;
    #pragma unroll
    for (int r = 0; r < 8; r++) {
        int ii = it * 64 + ty * 8 + r;
        float e = __expf(csb[ii * H]);
        float4* yp = reinterpret_cast<float4*>(g_y + (size_t)(bd * L + tbase + ii) * DIN + h * P) + tx;
        float4 v = *yp;
        v.x += e * acc[r][0]; v.y += e * acc[r][1];
        v.z += e * acc[r][2]; v.w += e * acc[r][3];
        *yp = v;
    }
}

// ---------------------------------------------------------------------------
// K7: gate = x @ W^T + D; out = roll(y_fw) + flip(roll(y_bw)) + x*repeat(gate)
// grid 2048 blocks: (bb, 4-timestep tile), 256 threads
// ---------------------------------------------------------------------------
__global__ void k_final(const float* __restrict__ x, const float* __restrict__ W,
                        const float* __restrict__ Dv, float* __restrict__ out)
{
    int blk = blockIdx.x;
    int bb = blk >> 10;
    int t0 = (blk & 1023) * 4;
    int tid = threadIdx.x;

    __shared__ __align__(16) float xs[4 * DIN];
    __shared__ float gates[4][H];

    #pragma unroll
    for (int r = 0; r < 8; r++) {
        int e4 = tid + 256 * r;                 // 2048 float4 = 4 rows x 512
        int tt = e4 >> 9, d4 = e4 & 511;
        reinterpret_cast<float4*>(xs)[e4] =
            reinterpret_cast<const float4*>(x + (size_t)(bb * L + t0 + tt) * DIN)[d4];
    }
    __syncthreads();

    int w = tid >> 5, lane = tid & 31;
    #pragma unroll
    for (int e = 0; e < 2; e++) {
        int hh = w * 2 + e;
        float p0 = 0.f, p1 = 0.f, p2 = 0.f, p3 = 0.f;
        for (int d = lane; d < DIN; d += 32) {
            float wv = W[(size_t)hh * DIN + d];
            p0 += xs[0 * DIN + d] * wv;
            p1 += xs[1 * DIN + d] * wv;
            p2 += xs[2 * DIN + d] * wv;
            p3 += xs[3 * DIN + d] * wv;
        }
        #pragma unroll
        for (int off = 16; off > 0; off >>= 1) {
            p0 += __shfl_xor_sync(0xffffffffu, p0, off);
            p1 += __shfl_xor_sync(0xffffffffu, p1, off);
            p2 += __shfl_xor_sync(0xffffffffu, p2, off);
            p3 += __shfl_xor_sync(0xffffffffu, p3, off);
        }
        if (lane == 0) {
            float dd = Dv[hh];
            gates[0][hh] = p0 + dd; gates[1][hh] = p1 + dd;
            gates[2][hh] = p2 + dd; gates[3][hh] = p3 + dd;
        }
    }
    __syncthreads();

    #pragma unroll
    for (int r = 0; r < 8; r++) {
        int e4 = tid + 256 * r;
        int tt = e4 >> 9, d4 = e4 & 511;
        int t = t0 + tt;
        int d = d4 * 4, h = d >> 7;
        float4 yf = make_float4(0.f, 0.f, 0.f, 0.f);
        float4 yb = make_float4(0.f, 0.f, 0.f, 0.f);
        if (t > 0)
            yf = reinterpret_cast<const float4*>(g_y + (size_t)(bb * L + t - 1) * DIN)[d4];
        if (t < L - 1)
            yb = reinterpret_cast<const float4*>(g_y + (size_t)((2 + bb) * L + (L - 2 - t)) * DIN)[d4];
        float gt = gates[tt][h];
        float4 xv = reinterpret_cast<const float4*>(xs)[e4];
        float4 o;
        o.x = yf.x + yb.x + xv.x * gt;
        o.y = yf.y + yb.y + xv.y * gt;
        o.z = yf.z + yb.z + xv.z * gt;
        o.w = yf.w + yb.w + xv.w * gt;
        reinterpret_cast<float4*>(out + (size_t)(bb * L + t) * DIN)[d4] = o;
    }
}

// ---------------------------------------------------------------------------
extern "C" void kernel_launch(void* const* d_in, const int* in_sizes, int n_in,
                              void* d_out, int out_size)
{
    const float* x     = (const float*)d_in[0];   // (2,4096,2048)
    const float* BC    = (const float*)d_in[1];   // (2,4096,512)
    const float* dt    = (const float*)d_in[2];   // (2,4096,32)
    const float* A_log = (const float*)d_in[3];   // (16,)
    const float* Dv    = (const float*)d_in[4];   // (16,)
    const float* W     = (const float*)d_in[5];   // (16,2048)
    float* out = (float*)d_out;

    k_prep  <<<dim3(NC, BD),     256>>>(dt, A_log);
    k_cb    <<<dim3(4, 4, 64),   256>>>(BC);
    k_yintra<<<dim3(4, H, 64),   256>>>(x);
    k_states<<<dim3(4, H, 64),   256>>>(x, BC);
    k_scan  <<<8192,             256>>>();
    k_yinter<<<dim3(4, H, 64),   256>>>(BC);
    k_final <<<2048,             256>>>(x, W, Dv, out);
}